// round 12
// baseline (speedup 1.0000x reference)
#include <cuda_runtime.h>
#include <cuda_bf16.h>

#define L 4
#define B 128
#define T 1024
#define NI 512
#define H 512
#define G 2048
#define BH (B*H)

#define NBLK 128
#define NTHR 512

// ---- smem layout (bytes) ----
// x-phase: W 64 rows x 512k hi/lo @0 (stride 1040), PS double-buffer @133120
#define WS_HI 0
#define WS_LO 66560
#define PS 133120
#define PLANE 18432
#define BUFSTRIDE 36864
// recurrent: W stage 32 rows hi@0 lo@33280 (hoisted to regs), then:
//   stage A @0, stage B @66560 (each: hi plane + lo plane @+33280, 32 rows x 1040)
//   gbufs: A @133120, B @150528 (each 4 wsub x 32x34 f32 = 17408B)
#define RLO 33280
#define SB_A 0
#define SB_B 66560
#define GB_A 133120
#define GB_B 150528
#define GBUF_W (32*34)
#define SMEM_BYTES 215296

// ---- device scratch: pre-split hi/lo bf16 planes ----
__device__ __nv_bfloat16 g_x_hi[(size_t)B * T * NI];    // [b][t][k]
__device__ __nv_bfloat16 g_x_lo[(size_t)B * T * NI];
__device__ __nv_bfloat16 g_seq_hi[(size_t)T * BH];      // [t][b][k]
__device__ __nv_bfloat16 g_seq_lo[(size_t)T * BH];
__device__ __nv_bfloat16 g_h0_hi[(size_t)L * BH];
__device__ __nv_bfloat16 g_h0_lo[(size_t)L * BH];
__device__ float g_gx[(size_t)B * T * G];               // [t][b][gate]
__device__ unsigned long long g_flags[NBLK];            // phase-transition barrier
__device__ unsigned long long g_flagsA[NBLK];           // chain-A per-step flags
__device__ unsigned long long g_flagsB[NBLK];           // chain-B per-step flags

#define CP_ASYNC16(dst, src) \
    asm volatile("cp.async.cg.shared.global [%0], [%1], 16;" :: "r"(dst), "l"(src))
#define CP_COMMIT() asm volatile("cp.async.commit_group;" ::: "memory")
#define CP_WAIT0()  asm volatile("cp.async.wait_group 0;" ::: "memory")

__device__ __forceinline__ unsigned long long ldvol(const unsigned long long* p) {
    unsigned long long v;
    asm volatile("ld.volatile.global.u64 %0, [%1];" : "=l"(v) : "l"(p));
    return v;
}

// global barrier (prologue + phase transitions)
__device__ __forceinline__ void gbar_all(unsigned long long ep) {
    __syncthreads();
    __threadfence();
    if (threadIdx.x == 0) atomicExch(&g_flags[blockIdx.x], ep);
    if (threadIdx.x < NBLK) {
        while (ldvol(&g_flags[threadIdx.x]) < ep) { }
    }
    __threadfence();
    __syncthreads();
}

// fp32x4 -> hi/lo bf16 plane pairs (uint2 = 4 bf16)
__device__ __forceinline__ void split4(float4 v, uint2& hi, uint2& lo) {
    __nv_bfloat16 h0 = __float2bfloat16(v.x), h1 = __float2bfloat16(v.y);
    __nv_bfloat16 h2 = __float2bfloat16(v.z), h3 = __float2bfloat16(v.w);
    __nv_bfloat16 l0 = __float2bfloat16(v.x - __bfloat162float(h0));
    __nv_bfloat16 l1 = __float2bfloat16(v.y - __bfloat162float(h1));
    __nv_bfloat16 l2 = __float2bfloat16(v.z - __bfloat162float(h2));
    __nv_bfloat16 l3 = __float2bfloat16(v.w - __bfloat162float(h3));
    hi.x = (unsigned)*(unsigned short*)&h0 | ((unsigned)*(unsigned short*)&h1 << 16);
    hi.y = (unsigned)*(unsigned short*)&h2 | ((unsigned)*(unsigned short*)&h3 << 16);
    lo.x = (unsigned)*(unsigned short*)&l0 | ((unsigned)*(unsigned short*)&l1 << 16);
    lo.y = (unsigned)*(unsigned short*)&l2 | ((unsigned)*(unsigned short*)&l3 << 16);
}

__device__ __forceinline__ void ldsm4(unsigned r[4], unsigned addr) {
    asm volatile("ldmatrix.sync.aligned.m8n8.x4.shared.b16 {%0,%1,%2,%3}, [%4];"
                 : "=r"(r[0]), "=r"(r[1]), "=r"(r[2]), "=r"(r[3]) : "r"(addr));
}

__device__ __forceinline__ void mma16816(float c[4], const unsigned a[4],
                                         unsigned b0, unsigned b1) {
    asm volatile(
        "mma.sync.aligned.m16n8k16.row.col.f32.bf16.bf16.f32 "
        "{%0,%1,%2,%3}, {%4,%5,%6,%7}, {%8,%9}, {%0,%1,%2,%3};"
        : "+f"(c[0]), "+f"(c[1]), "+f"(c[2]), "+f"(c[3])
        : "r"(a[0]), "r"(a[1]), "r"(a[2]), "r"(a[3]), "r"(b0), "r"(b1));
}

__device__ __forceinline__ float sigf(float x) { return 1.0f / (1.0f + __expf(-x)); }
__device__ __forceinline__ float tanhg(float x) { return 2.0f / (1.0f + __expf(-2.0f * x)) - 1.0f; }

// one interleaved recurrent phase: one timestep for one batch group
__device__ __forceinline__ void rec_phase(
    char* sm, unsigned sbase, int tid, int lane,
    int wg2, int wn, int wsub2, int p, int g, int l, int t, int gt2,
    unsigned SB, unsigned GBoff,
    unsigned long long* flags, unsigned long long baseEp,
    const unsigned (&ahh)[8][4], const unsigned (&alo)[8][4],
    const float (&bias)[4], float& creg,
    float* out)
{
    const int rr0 = tid >> 6, rsg = tid & 63;
    const int hl = tid & 7, bl_ = (tid >> 3) & 31;
    const int egh = gt2 * 8 + hl;
    const int ebb = g * 32 + bl_;

    // wait for peers' h(t-1) of this chain
    if (tid < 64) {
        while (ldvol(&flags[p * 64 + tid]) < baseEp + (unsigned long long)t) { }
    }
    __threadfence();
    __syncthreads();

    // stage h(t-1) tile (32 b x 512 k, hi/lo) via cp.async
    {
        const __nv_bfloat16 *hiP, *loP;
        size_t rowe;
        if (t == 0) {
            hiP = g_h0_hi; loP = g_h0_lo;
            rowe = ((size_t)(l * 128 + g * 32 + rr0)) * 512;
        } else {
            hiP = g_seq_hi; loP = g_seq_lo;
            rowe = ((size_t)((t - 1) * 128 + g * 32 + rr0)) * 512;
        }
        #pragma unroll
        for (int i = 0; i < 4; ++i) {
            const unsigned d = sbase + SB + (rr0 + i * 8) * 1040 + rsg * 16;
            const size_t s = rowe + (size_t)(i * 8) * 512 + rsg * 8;
            CP_ASYNC16(d,       hiP + s);
            CP_ASYNC16(d + RLO, loP + s);
        }
        CP_COMMIT();
    }

    // prefetch gx (hidden under the copy + mma)
    float gx0 = 0.f, gx1 = 0.f, gx2 = 0.f, gx3 = 0.f;
    if (tid < 256) {
        const float* gxt = g_gx + ((size_t)t * 128 + ebb) * G + egh;
        gx0 = __ldcg(gxt);
        gx1 = __ldcg(gxt + 512);
        gx2 = __ldcg(gxt + 1024);
        gx3 = __ldcg(gxt + 1536);
    }

    CP_WAIT0();
    __syncthreads();

    // mma: warp = m16 (wg2) x n16 (wn) x K128 (wsub2); A from registers
    float a0[2][4] = {{0.f,0.f,0.f,0.f},{0.f,0.f,0.f,0.f}};
    float a1[2][4] = {{0.f,0.f,0.f,0.f},{0.f,0.f,0.f,0.f}};
    #pragma unroll
    for (int nt = 0; nt < 2; ++nt) {
        const unsigned pB = sbase + SB +
            (unsigned)((wn * 16 + nt * 8 + (lane & 7)) * 1040 + (lane >> 3) * 16 + wsub2 * 256);
        #pragma unroll
        for (int c2 = 0; c2 < 4; ++c2) {
            unsigned bh[4], bl[4];
            ldsm4(bh, pB + c2 * 64);
            ldsm4(bl, pB + c2 * 64 + RLO);
            mma16816(a0[nt], ahh[2 * c2],     bh[0], bh[1]);
            mma16816(a1[nt], alo[2 * c2],     bh[0], bh[1]);
            mma16816(a1[nt], ahh[2 * c2],     bl[0], bl[1]);
            mma16816(a0[nt], ahh[2 * c2 + 1], bh[2], bh[3]);
            mma16816(a1[nt], alo[2 * c2 + 1], bh[2], bh[3]);
            mma16816(a1[nt], ahh[2 * c2 + 1], bl[2], bl[3]);
        }
    }

    // K-split partials -> per-wsub gate buffer
    {
        float* gb = (float*)(sm + GBoff) + wsub2 * GBUF_W;
        const int gr = wg2 * 16 + (lane >> 2);
        const int gc = (lane & 3) * 2;
        #pragma unroll
        for (int nt = 0; nt < 2; ++nt) {
            const int col = wn * 16 + nt * 8 + gc;
            *(float2*)&gb[gr * 34 + col] =
                make_float2(a0[nt][0] + a1[nt][0], a0[nt][1] + a1[nt][1]);
            *(float2*)&gb[(gr + 8) * 34 + col] =
                make_float2(a0[nt][2] + a1[nt][2], a0[nt][3] + a1[nt][3]);
        }
    }
    __syncthreads();

    // elementwise (256 threads: 8 h x 32 b)
    if (tid < 256) {
        float v0 = bias[0] + gx0;
        float v1 = bias[1] + gx1;
        float v2 = bias[2] + gx2;
        float v3 = bias[3] + gx3;
        #pragma unroll
        for (int s = 0; s < 4; ++s) {
            const float* gb = (const float*)(sm + GBoff) + s * GBUF_W;
            v0 += gb[(0 * 8 + hl) * 34 + bl_];
            v1 += gb[(1 * 8 + hl) * 34 + bl_];
            v2 += gb[(2 * 8 + hl) * 34 + bl_];
            v3 += gb[(3 * 8 + hl) * 34 + bl_];
        }
        float ig = sigf(v0), fg = sigf(v1), gg = tanhg(v2), og = sigf(v3);
        creg = fmaf(fg, creg, ig * gg);
        float hv = og * tanhg(creg);
        size_t hidx = ((size_t)t * 128 + ebb) * 512 + egh;
        __nv_bfloat16 hb = __float2bfloat16(hv);
        __nv_bfloat16 hw = __float2bfloat16(hv - __bfloat162float(hb));
        g_seq_hi[hidx] = hb;
        g_seq_lo[hidx] = hw;
        if (t == T - 1)
            out[(size_t)l * BH + (size_t)ebb * 512 + egh] = creg;
    }

    // publish h(t) for this chain
    __syncthreads();
    __threadfence();
    if (tid == 0) atomicExch(&flags[blockIdx.x], baseEp + (unsigned long long)(t + 1));
}

__global__ void __launch_bounds__(NTHR, 1)
lstm_kernel(const float* __restrict__ x,
            const float* __restrict__ h0,
            const float* __restrict__ c0,
            const float* __restrict__ w_ih,
            const float* __restrict__ w_hh,
            const float* __restrict__ b_ih,
            const float* __restrict__ b_hh,
            float* __restrict__ out) {
    extern __shared__ char sm[];
    const unsigned sbase = (unsigned)__cvta_generic_to_shared(sm);

    const int tid = threadIdx.x, bid = blockIdx.x;
    const int lane = tid & 31, warp = tid >> 5;

    unsigned long long ep = ldvol(&g_flags[bid]);

    // ---------------- prologue: split x, h0 into hi/lo planes ----------------
    {
        const size_t gt0 = (size_t)bid * NTHR + tid, gs = (size_t)NBLK * NTHR;
        const float4* xs = (const float4*)x;
        const size_t nx = (size_t)B * T * NI / 4;
        for (size_t i = gt0; i < nx; i += gs) {
            uint2 hi, lo;
            split4(__ldg(xs + i), hi, lo);
            ((uint2*)g_x_hi)[i] = hi;
            ((uint2*)g_x_lo)[i] = lo;
        }
        const float4* hs = (const float4*)h0;
        const size_t nh = (size_t)L * BH / 4;
        for (size_t i = gt0; i < nh; i += gs) {
            uint2 hi, lo;
            split4(__ldg(hs + i), hi, lo);
            ((uint2*)g_h0_hi)[i] = hi;
            ((uint2*)g_h0_lo)[i] = lo;
        }
    }
    gbar_all(++ep);

    // x-phase mapping (unchanged from R11)
    const int gt = bid & 31;
    const int grp = bid >> 5;
    const int wg = warp >> 2, wsub = warp & 3;
    const unsigned wA = sbase + WS_HI + (unsigned)((wg * 16 + (lane & 15)) * 1040 + (lane >> 4) * 16);
    const unsigned wAlo = wA + (WS_LO - WS_HI);
    const unsigned pBx_rel = (unsigned)((wsub * 32 + (lane & 7) + ((lane >> 4) << 3)) * 144
                                        + ((lane >> 3) & 1) * 16);
    const int xr0 = tid >> 3, xs0 = tid & 7;
    const int xr1 = (tid + 512) >> 3, xs1 = tid & 7;

    // recurrent mapping: 64 h-octets x 2 p-sets; block serves groups p and p+2
    const int gt2 = bid & 63;
    const int p = bid >> 6;
    const int gA = p, gB = p + 2;
    const int wg2 = warp >> 3, wn = (warp >> 2) & 1, wsub2 = warp & 3;
    const int hl = tid & 7;
    const int egh = gt2 * 8 + hl;

    for (int l = 0; l < L; ++l) {
        // ================= x-phase: gx = W_ih * input_seq =================
        for (int it = tid; it < 64 * 128; it += NTHR) {
            int r = it >> 7, c4 = it & 127;
            float4 v = __ldg((const float4*)(w_ih + ((size_t)l * G + gt * 64 + r) * 512) + c4);
            uint2 hi, lo;
            split4(v, hi, lo);
            *(uint2*)(sm + WS_HI + r * 1040 + c4 * 8) = hi;
            *(uint2*)(sm + WS_LO + r * 1040 + c4 * 8) = lo;
        }
        __syncthreads();

        {
            for (int m = 0; m < 256; ++m) {
                const int bb = grp * 32 + (m >> 3);
                const int t0 = (m & 7) * 128;

                const __nv_bfloat16 *hiP, *loP;
                size_t rb0, rb1;
                if (l == 0) {
                    hiP = g_x_hi; loP = g_x_lo;
                    rb0 = (((size_t)bb << 10) + (size_t)(t0 + xr0)) * 512;
                    rb1 = (((size_t)bb << 10) + (size_t)(t0 + xr1)) * 512;
                } else {
                    hiP = g_seq_hi; loP = g_seq_lo;
                    rb0 = ((size_t)((t0 + xr0) * 128 + bb)) * 512;
                    rb1 = ((size_t)((t0 + xr1) * 128 + bb)) * 512;
                }

                float acc[4][4];
                #pragma unroll
                for (int f = 0; f < 4; ++f)
                    #pragma unroll
                    for (int q = 0; q < 4; ++q) acc[f][q] = 0.f;

                {
                    const unsigned d0 = sbase + PS + xr0 * 144 + xs0 * 16;
                    const unsigned d1 = sbase + PS + xr1 * 144 + xs1 * 16;
                    CP_ASYNC16(d0,          hiP + rb0 + xs0 * 8);
                    CP_ASYNC16(d0 + PLANE,  loP + rb0 + xs0 * 8);
                    CP_ASYNC16(d1,          hiP + rb1 + xs1 * 8);
                    CP_ASYNC16(d1 + PLANE,  loP + rb1 + xs1 * 8);
                    CP_COMMIT();
                }

                #pragma unroll 1
                for (int c = 0; c < 8; ++c) {
                    CP_WAIT0();
                    __syncthreads();
                    if (c < 7) {
                        const int k0 = (c + 1) * 64;
                        const unsigned bufd = sbase + PS + ((c + 1) & 1) * BUFSTRIDE;
                        const unsigned d0 = bufd + xr0 * 144 + xs0 * 16;
                        const unsigned d1 = bufd + xr1 * 144 + xs1 * 16;
                        CP_ASYNC16(d0,          hiP + rb0 + k0 + xs0 * 8);
                        CP_ASYNC16(d0 + PLANE,  loP + rb0 + k0 + xs0 * 8);
                        CP_ASYNC16(d1,          hiP + rb1 + k0 + xs1 * 8);
                        CP_ASYNC16(d1 + PLANE,  loP + rb1 + k0 + xs1 * 8);
                        CP_COMMIT();
                    }
                    const unsigned bufo = sbase + PS + (c & 1) * BUFSTRIDE;
                    #pragma unroll
                    for (int q = 0; q < 4; ++q) {
                        unsigned ah[4], al[4];
                        ldsm4(ah, wA + c * 128 + q * 32);
                        ldsm4(al, wAlo + c * 128 + q * 32);
                        #pragma unroll
                        for (int u = 0; u < 2; ++u) {
                            unsigned bh[4], bl[4];
                            unsigned ba = bufo + pBx_rel + u * 2304 + q * 32;
                            ldsm4(bh, ba);
                            ldsm4(bl, ba + PLANE);
                            mma16816(acc[2 * u],     ah, bh[0], bh[1]);
                            mma16816(acc[2 * u],     al, bh[0], bh[1]);
                            mma16816(acc[2 * u],     ah, bl[0], bl[1]);
                            mma16816(acc[2 * u + 1], ah, bh[2], bh[3]);
                            mma16816(acc[2 * u + 1], al, bh[2], bh[3]);
                            mma16816(acc[2 * u + 1], ah, bl[2], bl[3]);
                        }
                    }
                }

                const int gr0g = gt * 64 + wg * 16 + (lane >> 2);
                #pragma unroll
                for (int f = 0; f < 4; ++f) {
                    int u = f >> 1, v2 = f & 1;
                    int tt = wsub * 32 + u * 16 + v2 * 8 + (lane & 3) * 2;
                    size_t base = ((size_t)(t0 + tt) * 128 + bb) * (size_t)G + gr0g;
                    __stcg(g_gx + base,                        acc[f][0]);
                    __stcg(g_gx + base + (size_t)128 * G,      acc[f][1]);
                    __stcg(g_gx + base + 8,                    acc[f][2]);
                    __stcg(g_gx + base + (size_t)128 * G + 8,  acc[f][3]);
                }
                __syncthreads();
            }
        }
        gbar_all(++ep);

        // ================= recurrent phase (two interleaved chains) =================
        // stage W_hh: 32 gate rows x 512 k; local row r -> gate row (r>>3)*512 + gt2*8 + (r&7)
        for (int it = tid; it < 32 * 128; it += NTHR) {
            int r = it >> 7, c4 = it & 127;
            int grow = (r >> 3) * 512 + gt2 * 8 + (r & 7);
            float4 v = __ldg((const float4*)(w_hh + ((size_t)l * G + grow) * 512) + c4);
            uint2 hi, lo;
            split4(v, hi, lo);
            *(uint2*)(sm + r * 1040 + c4 * 8) = hi;
            *(uint2*)(sm + RLO + r * 1040 + c4 * 8) = lo;
        }
        __syncthreads();

        // hoist W_hh fragments (m16 x K128 per warp, hi+lo)
        unsigned ahh[8][4], alo[8][4];
        {
            const unsigned wAr = sbase + (unsigned)((wg2 * 16 + (lane & 15)) * 1040
                                                    + (lane >> 4) * 16 + wsub2 * 256);
            #pragma unroll
            for (int c = 0; c < 8; ++c) {
                ldsm4(ahh[c], wAr + c * 32);
                ldsm4(alo[c], wAr + RLO + c * 32);
            }
        }
        __syncthreads();   // W smem dead -> stage buffers overlay it

        float bias[4] = {0.f, 0.f, 0.f, 0.f};
        float cregA = 0.f, cregB = 0.f;
        if (tid < 256) {
            #pragma unroll
            for (int q = 0; q < 4; ++q)
                bias[q] = __ldg(b_ih + (size_t)l * G + q * 512 + egh)
                        + __ldg(b_hh + (size_t)l * G + q * 512 + egh);
            const int bl_ = (tid >> 3) & 31;
            cregA = __ldg(c0 + (size_t)l * BH + (size_t)(gA * 32 + bl_) * 512 + egh);
            cregB = __ldg(c0 + (size_t)l * BH + (size_t)(gB * 32 + bl_) * 512 + egh);
        }

        const unsigned long long bA = ldvol(&g_flagsA[bid]);
        const unsigned long long bB = ldvol(&g_flagsB[bid]);

        for (int t = 0; t < T; ++t) {
            rec_phase(sm, sbase, tid, lane, wg2, wn, wsub2, p, gA, l, t, gt2,
                      SB_A, GB_A, g_flagsA, bA, ahh, alo, bias, cregA, out);
            rec_phase(sm, sbase, tid, lane, wg2, wn, wsub2, p, gB, l, t, gt2,
                      SB_B, GB_B, g_flagsB, bB, ahh, alo, bias, cregB, out);
        }
        gbar_all(++ep);
    }
}

extern "C" void kernel_launch(void* const* d_in, const int* in_sizes, int n_in,
                              void* d_out, int out_size) {
    const float* x    = (const float*)d_in[0];
    const float* h0   = (const float*)d_in[1];
    const float* c0   = (const float*)d_in[2];
    const float* w_ih = (const float*)d_in[3];
    const float* w_hh = (const float*)d_in[4];
    const float* b_ih = (const float*)d_in[5];
    const float* b_hh = (const float*)d_in[6];
    float* out = (float*)d_out;

    cudaFuncSetAttribute(lstm_kernel,
                         cudaFuncAttributeMaxDynamicSharedMemorySize, SMEM_BYTES);
    lstm_kernel<<<NBLK, NTHR, SMEM_BYTES>>>(x, h0, c0, w_ih, w_hh, b_ih, b_hh, out);
}

// round 13
// speedup vs baseline: 1.3687x; 1.3687x over previous
#include <cuda_runtime.h>
#include <cuda_bf16.h>

#define L 4
#define B 128
#define T 1024
#define NI 512
#define H 512
#define G 2048
#define BH (B*H)

#define NBLK 128
#define NTHR 512

// ---- smem layout (bytes) ----
// W: 64 rows x 512k hi/lo planes, row stride 1040B
#define WS_HI 0
#define WS_LO 66560
// x-phase stage: 2 buffers x (hi+lo planes), plane = 128 rows x 144B
#define PS 133120
#define PLANE 18432
#define BUFSTRIDE 36864
// recurrent stage: one 66560B block (hi 32x1040 @RS, lo @RS+33280)
#define RS 133120
#define RPLANE 33280
#define MBAR 213120
#define SMEM_BYTES 215296
// recurrent K-split gate buffers: 4 x (64 x 34 f32), overlaid on dead W region
#define GBUF_STRIDE (64 * 34)

// seq block geometry: per (t, grp): hi plane 32rows x 1040B, lo plane at +33280
#define SEQBLK 66560
#define ROWB 1040
#define LOFF 33280

// ---- device scratch ----
__device__ __nv_bfloat16 g_x_hi[(size_t)B * T * NI];                 // [b][t][k] flat
__device__ __nv_bfloat16 g_x_lo[(size_t)B * T * NI];
__device__ __align__(128) unsigned char g_seqblk[(size_t)T * 4 * SEQBLK];  // [t][grp] smem-image
__device__ __align__(128) unsigned char g_h0blk[(size_t)L * 4 * SEQBLK];   // [l][grp] smem-image
__device__ float g_gx[(size_t)B * T * G];                            // [t][b][gate]
__device__ unsigned long long g_flags[NBLK];

#define CP_ASYNC16(dst, src) \
    asm volatile("cp.async.cg.shared.global [%0], [%1], 16;" :: "r"(dst), "l"(src))
#define CP_COMMIT() asm volatile("cp.async.commit_group;" ::: "memory")
#define CP_WAIT0()  asm volatile("cp.async.wait_group 0;" ::: "memory")

__device__ __forceinline__ unsigned long long ldvol(const unsigned long long* p) {
    unsigned long long v;
    asm volatile("ld.volatile.global.u64 %0, [%1];" : "=l"(v) : "l"(p));
    return v;
}

// global barrier (prologue only)
__device__ __forceinline__ void gbar_all(unsigned long long ep) {
    __syncthreads();
    __threadfence();
    if (threadIdx.x == 0) atomicExch(&g_flags[blockIdx.x], ep);
    if (threadIdx.x < NBLK) {
        while (ldvol(&g_flags[threadIdx.x]) < ep) { }
    }
    __threadfence();
    __syncthreads();
}

// group barrier: 32 blocks sharing a batch group
__device__ __forceinline__ void gbar_grp(unsigned long long ep, int grp) {
    __syncthreads();
    __threadfence();
    if (threadIdx.x == 0) atomicExch(&g_flags[blockIdx.x], ep);
    if (threadIdx.x < 32) {
        while (ldvol(&g_flags[grp * 32 + threadIdx.x]) < ep) { }
    }
    __threadfence();
    __syncthreads();
}

__device__ __forceinline__ void mbar_wait(unsigned mbar, unsigned phase) {
    asm volatile(
        "{\n\t"
        ".reg .pred P;\n\t"
        "WL_%=:\n\t"
        "mbarrier.try_wait.parity.shared.b64 P, [%0], %1;\n\t"
        "@!P bra WL_%=;\n\t"
        "}"
        :: "r"(mbar), "r"(phase) : "memory");
}

// fp32x4 -> hi/lo bf16 plane pairs (uint2 = 4 bf16)
__device__ __forceinline__ void split4(float4 v, uint2& hi, uint2& lo) {
    __nv_bfloat16 h0 = __float2bfloat16(v.x), h1 = __float2bfloat16(v.y);
    __nv_bfloat16 h2 = __float2bfloat16(v.z), h3 = __float2bfloat16(v.w);
    __nv_bfloat16 l0 = __float2bfloat16(v.x - __bfloat162float(h0));
    __nv_bfloat16 l1 = __float2bfloat16(v.y - __bfloat162float(h1));
    __nv_bfloat16 l2 = __float2bfloat16(v.z - __bfloat162float(h2));
    __nv_bfloat16 l3 = __float2bfloat16(v.w - __bfloat162float(h3));
    hi.x = (unsigned)*(unsigned short*)&h0 | ((unsigned)*(unsigned short*)&h1 << 16);
    hi.y = (unsigned)*(unsigned short*)&h2 | ((unsigned)*(unsigned short*)&h3 << 16);
    lo.x = (unsigned)*(unsigned short*)&l0 | ((unsigned)*(unsigned short*)&l1 << 16);
    lo.y = (unsigned)*(unsigned short*)&l2 | ((unsigned)*(unsigned short*)&l3 << 16);
}

__device__ __forceinline__ void ldsm4(unsigned r[4], unsigned addr) {
    asm volatile("ldmatrix.sync.aligned.m8n8.x4.shared.b16 {%0,%1,%2,%3}, [%4];"
                 : "=r"(r[0]), "=r"(r[1]), "=r"(r[2]), "=r"(r[3]) : "r"(addr));
}

__device__ __forceinline__ void mma16816(float c[4], const unsigned a[4],
                                         unsigned b0, unsigned b1) {
    asm volatile(
        "mma.sync.aligned.m16n8k16.row.col.f32.bf16.bf16.f32 "
        "{%0,%1,%2,%3}, {%4,%5,%6,%7}, {%8,%9}, {%0,%1,%2,%3};"
        : "+f"(c[0]), "+f"(c[1]), "+f"(c[2]), "+f"(c[3])
        : "r"(a[0]), "r"(a[1]), "r"(a[2]), "r"(a[3]), "r"(b0), "r"(b1));
}

__device__ __forceinline__ float sigf(float x) { return 1.0f / (1.0f + __expf(-x)); }
__device__ __forceinline__ float tanhg(float x) { return 2.0f / (1.0f + __expf(-2.0f * x)) - 1.0f; }

__global__ void __launch_bounds__(NTHR, 1)
lstm_kernel(const float* __restrict__ x,
            const float* __restrict__ h0,
            const float* __restrict__ c0,
            const float* __restrict__ w_ih,
            const float* __restrict__ w_hh,
            const float* __restrict__ b_ih,
            const float* __restrict__ b_hh,
            float* __restrict__ out) {
    extern __shared__ char sm[];
    const unsigned sbase = (unsigned)__cvta_generic_to_shared(sm);

    const int tid = threadIdx.x, bid = blockIdx.x;
    const int lane = tid & 31, warp = tid >> 5;

    unsigned long long ep = ldvol(&g_flags[bid]);
    unsigned mpar = 0;   // mbarrier phase parity (flips every recurrent step)

    if (tid == 0)
        asm volatile("mbarrier.init.shared.b64 [%0], %1;" :: "r"(sbase + MBAR), "r"(1u));

    // ---------------- prologue: split x (flat), h0 (block format) ----------------
    {
        const size_t gt0 = (size_t)bid * NTHR + tid, gs = (size_t)NBLK * NTHR;
        const float4* xs = (const float4*)x;
        const size_t nx = (size_t)B * T * NI / 4;
        for (size_t i = gt0; i < nx; i += gs) {
            uint2 hi, lo;
            split4(__ldg(xs + i), hi, lo);
            ((uint2*)g_x_hi)[i] = hi;
            ((uint2*)g_x_lo)[i] = lo;
        }
        const float4* hs = (const float4*)h0;
        const size_t nh = (size_t)L * BH / 4;
        for (size_t i = gt0; i < nh; i += gs) {
            uint2 hi, lo;
            split4(__ldg(hs + i), hi, lo);
            size_t e = i * 4;
            int l_ = (int)(e >> 16);
            int b_ = (int)((e >> 9) & 127);
            int k_ = (int)(e & 511);
            size_t d = ((size_t)l_ * 4 + (size_t)(b_ >> 5)) * SEQBLK
                     + (size_t)(b_ & 31) * ROWB + (size_t)k_ * 2;
            *(uint2*)(g_h0blk + d) = hi;
            *(uint2*)(g_h0blk + d + LOFF) = lo;
        }
    }
    gbar_all(++ep);

    const int gt = bid & 31;    // gate/h tile
    const int grp = bid >> 5;   // batch group (32 batches)

    const int wg = warp >> 2, wsub = warp & 3;
    const unsigned wA = sbase + WS_HI + (unsigned)((wg * 16 + (lane & 15)) * 1040 + (lane >> 4) * 16);
    const unsigned wAlo = wA + (WS_LO - WS_HI);
    const unsigned pBx_rel = (unsigned)((wsub * 32 + (lane & 7) + ((lane >> 4) << 3)) * 144
                                        + ((lane >> 3) & 1) * 16);
    const unsigned pBrK = sbase + RS + (unsigned)((lane & 7) * 1040 + (lane >> 3) * 16 + wsub * 256);

    const int lh = tid & 15, lb = tid >> 4;
    const int eb = grp * 32 + lb;
    const int egh = gt * 16 + lh;

    const int xr0 = tid >> 3, xs0 = tid & 7;
    const int xr1 = (tid + 512) >> 3, xs1 = tid & 7;

    for (int l = 0; l < L; ++l) {
        // ================= x-phase: gx = W_ih * input_seq =================
        for (int it = tid; it < 64 * 128; it += NTHR) {
            int r = it >> 7, c4 = it & 127;
            float4 v = __ldg((const float4*)(w_ih + ((size_t)l * G + gt * 64 + r) * 512) + c4);
            uint2 hi, lo;
            split4(v, hi, lo);
            *(uint2*)(sm + WS_HI + r * 1040 + c4 * 8) = hi;
            *(uint2*)(sm + WS_LO + r * 1040 + c4 * 8) = lo;
        }
        __syncthreads();

        {
            for (int m = 0; m < 256; ++m) {
                const int bb = grp * 32 + (m >> 3);
                const int t0 = (m & 7) * 128;

                // per-row source byte pointers (k=0), same inner byte offsets both paths
                const unsigned char *sh0, *sl0, *sh1, *sl1;
                if (l == 0) {
                    size_t rb0 = (((size_t)bb << 10) + (size_t)(t0 + xr0)) * 512;
                    size_t rb1 = (((size_t)bb << 10) + (size_t)(t0 + xr1)) * 512;
                    sh0 = (const unsigned char*)(g_x_hi + rb0);
                    sl0 = (const unsigned char*)(g_x_lo + rb0);
                    sh1 = (const unsigned char*)(g_x_hi + rb1);
                    sl1 = (const unsigned char*)(g_x_lo + rb1);
                } else {
                    size_t b0 = ((size_t)(t0 + xr0) * 4 + grp) * SEQBLK + (size_t)(bb & 31) * ROWB;
                    size_t b1 = ((size_t)(t0 + xr1) * 4 + grp) * SEQBLK + (size_t)(bb & 31) * ROWB;
                    sh0 = g_seqblk + b0; sl0 = sh0 + LOFF;
                    sh1 = g_seqblk + b1; sl1 = sh1 + LOFF;
                }

                float acc[4][4];
                #pragma unroll
                for (int f = 0; f < 4; ++f)
                    #pragma unroll
                    for (int q = 0; q < 4; ++q) acc[f][q] = 0.f;

                {
                    const unsigned d0 = sbase + PS + xr0 * 144 + xs0 * 16;
                    const unsigned d1 = sbase + PS + xr1 * 144 + xs1 * 16;
                    CP_ASYNC16(d0,          sh0 + xs0 * 16);
                    CP_ASYNC16(d0 + PLANE,  sl0 + xs0 * 16);
                    CP_ASYNC16(d1,          sh1 + xs1 * 16);
                    CP_ASYNC16(d1 + PLANE,  sl1 + xs1 * 16);
                    CP_COMMIT();
                }

                #pragma unroll 1
                for (int c = 0; c < 8; ++c) {
                    CP_WAIT0();
                    __syncthreads();
                    if (c < 7) {
                        const int kb = (c + 1) * 128;   // bytes
                        const unsigned bufd = sbase + PS + ((c + 1) & 1) * BUFSTRIDE;
                        const unsigned d0 = bufd + xr0 * 144 + xs0 * 16;
                        const unsigned d1 = bufd + xr1 * 144 + xs1 * 16;
                        CP_ASYNC16(d0,          sh0 + kb + xs0 * 16);
                        CP_ASYNC16(d0 + PLANE,  sl0 + kb + xs0 * 16);
                        CP_ASYNC16(d1,          sh1 + kb + xs1 * 16);
                        CP_ASYNC16(d1 + PLANE,  sl1 + kb + xs1 * 16);
                        CP_COMMIT();
                    }
                    const unsigned bufo = sbase + PS + (c & 1) * BUFSTRIDE;
                    #pragma unroll
                    for (int q = 0; q < 4; ++q) {
                        unsigned ah[4], al[4];
                        ldsm4(ah, wA + c * 128 + q * 32);
                        ldsm4(al, wAlo + c * 128 + q * 32);
                        #pragma unroll
                        for (int u = 0; u < 2; ++u) {
                            unsigned bh[4], bl[4];
                            unsigned ba = bufo + pBx_rel + u * 2304 + q * 32;
                            ldsm4(bh, ba);
                            ldsm4(bl, ba + PLANE);
                            mma16816(acc[2 * u],     ah, bh[0], bh[1]);
                            mma16816(acc[2 * u],     al, bh[0], bh[1]);
                            mma16816(acc[2 * u],     ah, bl[0], bl[1]);
                            mma16816(acc[2 * u + 1], ah, bh[2], bh[3]);
                            mma16816(acc[2 * u + 1], al, bh[2], bh[3]);
                            mma16816(acc[2 * u + 1], ah, bl[2], bl[3]);
                        }
                    }
                }

                // store gx tile: layout [t][b][gate]
                const int gr0g = gt * 64 + wg * 16 + (lane >> 2);
                #pragma unroll
                for (int f = 0; f < 4; ++f) {
                    int u = f >> 1, v2 = f & 1;
                    int tt = wsub * 32 + u * 16 + v2 * 8 + (lane & 3) * 2;
                    size_t base = ((size_t)(t0 + tt) * 128 + bb) * (size_t)G + gr0g;
                    __stcg(g_gx + base,                        acc[f][0]);
                    __stcg(g_gx + base + (size_t)128 * G,      acc[f][1]);
                    __stcg(g_gx + base + 8,                    acc[f][2]);
                    __stcg(g_gx + base + (size_t)128 * G + 8,  acc[f][3]);
                }
                __syncthreads();
            }
        }
        gbar_grp(++ep, grp);

        // ================= recurrent phase =================
        // stage W_hh: local row r -> gate row (r>>4)*512 + gt*16 + (r&15)
        for (int it = tid; it < 64 * 128; it += NTHR) {
            int r = it >> 7, c4 = it & 127;
            int grow = (r >> 4) * 512 + gt * 16 + (r & 15);
            float4 v = __ldg((const float4*)(w_hh + ((size_t)l * G + grow) * 512) + c4);
            uint2 hi, lo;
            split4(v, hi, lo);
            *(uint2*)(sm + WS_HI + r * 1040 + c4 * 8) = hi;
            *(uint2*)(sm + WS_LO + r * 1040 + c4 * 8) = lo;
        }
        __syncthreads();

        // hoist this warp's W_hh fragments into registers (once per layer)
        unsigned ah[8][4], al[8][4];
        #pragma unroll
        for (int c = 0; c < 8; ++c) {
            ldsm4(ah[c], wA + wsub * 256 + c * 32);
            ldsm4(al[c], wAlo + wsub * 256 + c * 32);
        }
        __syncthreads();   // W smem now dead -> gate buffers overlay it

        float bias[4];
        #pragma unroll
        for (int g = 0; g < 4; ++g)
            bias[g] = __ldg(b_ih + (size_t)l * G + g * 512 + egh)
                    + __ldg(b_hh + (size_t)l * G + g * 512 + egh);
        float creg = __ldg(c0 + (size_t)l * BH + (size_t)eb * 512 + egh);
        const float* gx_base = g_gx + (size_t)eb * G + egh;   // [t][b][gate]

        const unsigned char* h0src = g_h0blk + ((size_t)l * 4 + grp) * SEQBLK;

        float* const gbuf = (float*)sm + wsub * GBUF_STRIDE;
        const int gr = wg * 16 + (lane >> 2);
        const int gc = (lane & 3) * 2;

        for (int t = 0; t < T; ++t) {
            // wait: peers published h(t-1)  (t=0 passes trivially)
            if (tid < 32) {
                while (ldvol(&g_flags[grp * 32 + tid]) < ep + (unsigned long long)t) { }
            }
            __threadfence();
            __syncthreads();

            // ONE bulk copy stages the whole 32b x 512k hi/lo tile
            if (tid == 0) {
                const unsigned char* src = (t == 0) ? h0src
                    : g_seqblk + ((size_t)(t - 1) * 4 + grp) * SEQBLK;
                asm volatile("mbarrier.arrive.expect_tx.shared.b64 _, [%0], %1;"
                             :: "r"(sbase + MBAR), "r"((unsigned)SEQBLK) : "memory");
                asm volatile(
                    "cp.async.bulk.shared::cluster.global.mbarrier::complete_tx::bytes "
                    "[%0], [%1], %2, [%3];"
                    :: "r"(sbase + RS), "l"(src), "r"((unsigned)SEQBLK), "r"(sbase + MBAR)
                    : "memory");
            }

            // prefetch gx while the bulk copy is in flight
            const float* gxt = gx_base + (size_t)t * (128 * G);
            float gx0 = __ldcg(gxt);
            float gx1 = __ldcg(gxt + 512);
            float gx2 = __ldcg(gxt + 1024);
            float gx3 = __ldcg(gxt + 1536);

            mbar_wait(sbase + MBAR, mpar);
            mpar ^= 1;

            // warp computes m16 x n32 over its K128 slice; A from registers
            float a0[4][4], a1[4][4];
            #pragma unroll
            for (int nt = 0; nt < 4; ++nt)
                #pragma unroll
                for (int q = 0; q < 4; ++q) { a0[nt][q] = 0.f; a1[nt][q] = 0.f; }

            #pragma unroll
            for (int nt = 0; nt < 4; ++nt) {
                const unsigned bbase = pBrK + nt * (8 * 1040);
                #pragma unroll
                for (int c2 = 0; c2 < 4; ++c2) {
                    unsigned bh[4], bl[4];
                    ldsm4(bh, bbase + c2 * 64);
                    ldsm4(bl, bbase + c2 * 64 + RPLANE);
                    mma16816(a0[nt], ah[2 * c2],     bh[0], bh[1]);
                    mma16816(a1[nt], al[2 * c2],     bh[0], bh[1]);
                    mma16816(a1[nt], ah[2 * c2],     bl[0], bl[1]);
                    mma16816(a0[nt], ah[2 * c2 + 1], bh[2], bh[3]);
                    mma16816(a1[nt], al[2 * c2 + 1], bh[2], bh[3]);
                    mma16816(a1[nt], ah[2 * c2 + 1], bl[2], bl[3]);
                }
            }

            // K-split partials -> per-wsub gate buffer
            #pragma unroll
            for (int nt = 0; nt < 4; ++nt) {
                *(float2*)&gbuf[gr * 34 + nt * 8 + gc] =
                    make_float2(a0[nt][0] + a1[nt][0], a0[nt][1] + a1[nt][1]);
                *(float2*)&gbuf[(gr + 8) * 34 + nt * 8 + gc] =
                    make_float2(a0[nt][2] + a1[nt][2], a0[nt][3] + a1[nt][3]);
            }
            __syncthreads();

            // elementwise: sum 4 K-split buffers + gx + bias
            {
                float v0 = bias[0] + gx0;
                float v1 = bias[1] + gx1;
                float v2 = bias[2] + gx2;
                float v3 = bias[3] + gx3;
                #pragma unroll
                for (int s = 0; s < 4; ++s) {
                    const float* gb = (const float*)sm + s * GBUF_STRIDE;
                    v0 += gb[(0 * 16 + lh) * 34 + lb];
                    v1 += gb[(1 * 16 + lh) * 34 + lb];
                    v2 += gb[(2 * 16 + lh) * 34 + lb];
                    v3 += gb[(3 * 16 + lh) * 34 + lb];
                }
                float ig = sigf(v0), fg = sigf(v1), gg = tanhg(v2), og = sigf(v3);
                creg = fmaf(fg, creg, ig * gg);
                float hv = og * tanhg(creg);
                // write h into smem-image block layout
                size_t d = ((size_t)t * 4 + grp) * SEQBLK + (size_t)lb * ROWB + (size_t)egh * 2;
                __nv_bfloat16 hb = __float2bfloat16(hv);
                __nv_bfloat16 hw = __float2bfloat16(hv - __bfloat162float(hb));
                *(__nv_bfloat16*)(g_seqblk + d) = hb;
                *(__nv_bfloat16*)(g_seqblk + d + LOFF) = hw;
                if (t == T - 1)
                    out[(size_t)l * BH + (size_t)eb * 512 + egh] = creg;
            }

            // publish h(t)
            __syncthreads();
            __threadfence();
            if (tid == 0) atomicExch(&g_flags[bid], ep + (unsigned long long)(t + 1));
        }

        // drain: all group peers finished t = T-1 before next layer reads seq
        if (tid < 32) {
            while (ldvol(&g_flags[grp * 32 + tid]) < ep + (unsigned long long)T) { }
        }
        __threadfence();
        __syncthreads();
        ep += T;
    }
}

extern "C" void kernel_launch(void* const* d_in, const int* in_sizes, int n_in,
                              void* d_out, int out_size) {
    const float* x    = (const float*)d_in[0];
    const float* h0   = (const float*)d_in[1];
    const float* c0   = (const float*)d_in[2];
    const float* w_ih = (const float*)d_in[3];
    const float* w_hh = (const float*)d_in[4];
    const float* b_ih = (const float*)d_in[5];
    const float* b_hh = (const float*)d_in[6];
    float* out = (float*)d_out;

    cudaFuncSetAttribute(lstm_kernel,
                         cudaFuncAttributeMaxDynamicSharedMemorySize, SMEM_BYTES);
    lstm_kernel<<<NBLK, NTHR, SMEM_BYTES>>>(x, h0, c0, w_ih, w_hh, b_ih, b_hh, out);
}

// round 14
// speedup vs baseline: 1.4374x; 1.0502x over previous
#include <cuda_runtime.h>
#include <cuda_bf16.h>

#define L 4
#define B 128
#define T 1024
#define NI 512
#define H 512
#define G 2048
#define BH (B*H)

#define NBLK 128
#define NTHR 512

// ---- smem layout (bytes) ----
// W: 64 rows x 512k hi/lo planes, row stride 1040B
#define WS_HI 0
#define WS_LO 66560
// x-phase stage: 2 buffers x (hi+lo planes), plane = 128 rows x 144B
#define PS 133120
#define PLANE 18432
#define BUFSTRIDE 36864
// recurrent stage: 4 K-slices, each 17408B {hi 32x272, lo @+8704}
#define REC_STG 133120
#define SLICE 17408
#define HLO 8704
#define ROWB 272
#define GRPBLK (4*SLICE)
// K-split gate buffers overlay stage slices 0-1 (dead when gbuf live)
#define GBUF_STRIDE (64 * 34)
// 4 mbarriers (8B each) in reserved region untouched by either phase
#define MBAR_OFF 214528
#define SMEM_BYTES 215296

// ---- device scratch ----
__device__ __nv_bfloat16 g_x_hi[(size_t)B * T * NI];                 // [b][t][k] flat
__device__ __nv_bfloat16 g_x_lo[(size_t)B * T * NI];
__device__ __align__(128) unsigned char g_seqblk[(size_t)T * 4 * GRPBLK];  // [t][grp][s] sliced
__device__ __align__(128) unsigned char g_h0blk[(size_t)L * 4 * GRPBLK];   // [l][grp][s]
__device__ float g_gx[(size_t)B * T * G];                            // [t][b][gate]
__device__ unsigned long long g_flags[NBLK];

#define CP_ASYNC16(dst, src) \
    asm volatile("cp.async.cg.shared.global [%0], [%1], 16;" :: "r"(dst), "l"(src))
#define CP_COMMIT() asm volatile("cp.async.commit_group;" ::: "memory")
#define CP_WAIT0()  asm volatile("cp.async.wait_group 0;" ::: "memory")

__device__ __forceinline__ unsigned long long ldvol(const unsigned long long* p) {
    unsigned long long v;
    asm volatile("ld.volatile.global.u64 %0, [%1];" : "=l"(v) : "l"(p));
    return v;
}

__device__ __forceinline__ void gbar_all(unsigned long long ep) {
    __syncthreads();
    __threadfence();
    if (threadIdx.x == 0) atomicExch(&g_flags[blockIdx.x], ep);
    if (threadIdx.x < NBLK) {
        while (ldvol(&g_flags[threadIdx.x]) < ep) { }
    }
    __threadfence();
    __syncthreads();
}

__device__ __forceinline__ void gbar_grp(unsigned long long ep, int grp) {
    __syncthreads();
    __threadfence();
    if (threadIdx.x == 0) atomicExch(&g_flags[blockIdx.x], ep);
    if (threadIdx.x < 32) {
        while (ldvol(&g_flags[grp * 32 + threadIdx.x]) < ep) { }
    }
    __threadfence();
    __syncthreads();
}

__device__ __forceinline__ void mbar_wait(unsigned mbar, unsigned phase) {
    asm volatile(
        "{\n\t"
        ".reg .pred P;\n\t"
        "WL_%=:\n\t"
        "mbarrier.try_wait.parity.acquire.cta.shared::cta.b64 P, [%0], %1;\n\t"
        "@!P bra WL_%=;\n\t"
        "}"
        :: "r"(mbar), "r"(phase) : "memory");
}

__device__ __forceinline__ void split4(float4 v, uint2& hi, uint2& lo) {
    __nv_bfloat16 h0 = __float2bfloat16(v.x), h1 = __float2bfloat16(v.y);
    __nv_bfloat16 h2 = __float2bfloat16(v.z), h3 = __float2bfloat16(v.w);
    __nv_bfloat16 l0 = __float2bfloat16(v.x - __bfloat162float(h0));
    __nv_bfloat16 l1 = __float2bfloat16(v.y - __bfloat162float(h1));
    __nv_bfloat16 l2 = __float2bfloat16(v.z - __bfloat162float(h2));
    __nv_bfloat16 l3 = __float2bfloat16(v.w - __bfloat162float(h3));
    hi.x = (unsigned)*(unsigned short*)&h0 | ((unsigned)*(unsigned short*)&h1 << 16);
    hi.y = (unsigned)*(unsigned short*)&h2 | ((unsigned)*(unsigned short*)&h3 << 16);
    lo.x = (unsigned)*(unsigned short*)&l0 | ((unsigned)*(unsigned short*)&l1 << 16);
    lo.y = (unsigned)*(unsigned short*)&l2 | ((unsigned)*(unsigned short*)&l3 << 16);
}

__device__ __forceinline__ void ldsm4(unsigned r[4], unsigned addr) {
    asm volatile("ldmatrix.sync.aligned.m8n8.x4.shared.b16 {%0,%1,%2,%3}, [%4];"
                 : "=r"(r[0]), "=r"(r[1]), "=r"(r[2]), "=r"(r[3]) : "r"(addr));
}

__device__ __forceinline__ void mma16816(float c[4], const unsigned a[4],
                                         unsigned b0, unsigned b1) {
    asm volatile(
        "mma.sync.aligned.m16n8k16.row.col.f32.bf16.bf16.f32 "
        "{%0,%1,%2,%3}, {%4,%5,%6,%7}, {%8,%9}, {%0,%1,%2,%3};"
        : "+f"(c[0]), "+f"(c[1]), "+f"(c[2]), "+f"(c[3])
        : "r"(a[0]), "r"(a[1]), "r"(a[2]), "r"(a[3]), "r"(b0), "r"(b1));
}

__device__ __forceinline__ float sigf(float x) { return 1.0f / (1.0f + __expf(-x)); }
__device__ __forceinline__ float tanhg(float x) { return 2.0f / (1.0f + __expf(-2.0f * x)) - 1.0f; }

__global__ void __launch_bounds__(NTHR, 1)
lstm_kernel(const float* __restrict__ x,
            const float* __restrict__ h0,
            const float* __restrict__ c0,
            const float* __restrict__ w_ih,
            const float* __restrict__ w_hh,
            const float* __restrict__ b_ih,
            const float* __restrict__ b_hh,
            float* __restrict__ out) {
    extern __shared__ char sm[];
    const unsigned sbase = (unsigned)__cvta_generic_to_shared(sm);

    const int tid = threadIdx.x, bid = blockIdx.x;
    const int lane = tid & 31, warp = tid >> 5;

    unsigned long long ep = ldvol(&g_flags[bid]);
    unsigned mpar = 0;   // mbarrier parity, flips once per recurrent step

    if (tid < 4)
        asm volatile("mbarrier.init.shared.b64 [%0], %1;"
                     :: "r"(sbase + MBAR_OFF + tid * 8), "r"(1u));

    // ---------------- prologue: split x (flat), h0 (sliced block format) ----------------
    {
        const size_t gt0 = (size_t)bid * NTHR + tid, gs = (size_t)NBLK * NTHR;
        const float4* xs = (const float4*)x;
        const size_t nx = (size_t)B * T * NI / 4;
        for (size_t i = gt0; i < nx; i += gs) {
            uint2 hi, lo;
            split4(__ldg(xs + i), hi, lo);
            ((uint2*)g_x_hi)[i] = hi;
            ((uint2*)g_x_lo)[i] = lo;
        }
        const float4* hs = (const float4*)h0;
        const size_t nh = (size_t)L * BH / 4;
        for (size_t i = gt0; i < nh; i += gs) {
            uint2 hi, lo;
            split4(__ldg(hs + i), hi, lo);
            size_t e = i * 4;
            int l_ = (int)(e >> 16);
            int b_ = (int)((e >> 9) & 127);
            int k_ = (int)(e & 511);
            int s_ = k_ >> 7, kl = k_ & 127;
            size_t d = ((size_t)(l_ * 4 + (b_ >> 5)) * 4 + s_) * SLICE
                     + (size_t)(b_ & 31) * ROWB + (size_t)kl * 2;
            *(uint2*)(g_h0blk + d) = hi;
            *(uint2*)(g_h0blk + d + HLO) = lo;
        }
    }
    gbar_all(++ep);

    const int gt = bid & 31;    // gate/h tile
    const int grp = bid >> 5;   // batch group (32 batches)

    // x-phase warp roles
    const int wg = warp >> 2, wsub = warp & 3;
    const unsigned wA = sbase + WS_HI + (unsigned)((wg * 16 + (lane & 15)) * 1040 + (lane >> 4) * 16);
    const unsigned wAlo = wA + (WS_LO - WS_HI);
    const unsigned pBx_rel = (unsigned)((wsub * 32 + (lane & 7) + ((lane >> 4) << 3)) * 144
                                        + ((lane >> 3) & 1) * 16);
    const int xr0 = tid >> 3, xs0 = tid & 7;
    const int xr1 = (tid + 512) >> 3, xs1 = tid & 7;

    // recurrent warp roles: rwg = m-stripe, rws = K-slice; slice warps span 4 SMSPs
    const int rwg = warp & 3, rws = warp >> 2;
    const unsigned wAr = sbase + WS_HI + (unsigned)((rwg * 16 + (lane & 15)) * 1040
                                                    + (lane >> 4) * 16 + rws * 256);
    const unsigned wArlo = wAr + (WS_LO - WS_HI);
    const unsigned pBr = sbase + REC_STG + (unsigned)(rws * SLICE
                       + (lane & 7) * ROWB + (lane >> 3) * 16);
    const unsigned mbar_s = sbase + MBAR_OFF + rws * 8;

    const int lh = tid & 15, lb = tid >> 4;
    const int eb = grp * 32 + lb;
    const int egh = gt * 16 + lh;

    for (int l = 0; l < L; ++l) {
        const bool xflat = (l == 0);
        // ================= x-phase: gx = W_ih * input_seq =================
        for (int it = tid; it < 64 * 128; it += NTHR) {
            int r = it >> 7, c4 = it & 127;
            float4 v = __ldg((const float4*)(w_ih + ((size_t)l * G + gt * 64 + r) * 512) + c4);
            uint2 hi, lo;
            split4(v, hi, lo);
            *(uint2*)(sm + WS_HI + r * 1040 + c4 * 8) = hi;
            *(uint2*)(sm + WS_LO + r * 1040 + c4 * 8) = lo;
        }
        __syncthreads();

        {
            for (int m = 0; m < 256; ++m) {
                const int bb = grp * 32 + (m >> 3);
                const int t0 = (m & 7) * 128;

                const unsigned char *sh0, *sl0, *sh1, *sl1;
                if (xflat) {
                    size_t rb0 = (((size_t)bb << 10) + (size_t)(t0 + xr0)) * 512;
                    size_t rb1 = (((size_t)bb << 10) + (size_t)(t0 + xr1)) * 512;
                    sh0 = (const unsigned char*)(g_x_hi + rb0);
                    sl0 = (const unsigned char*)(g_x_lo + rb0);
                    sh1 = (const unsigned char*)(g_x_hi + rb1);
                    sl1 = (const unsigned char*)(g_x_lo + rb1);
                } else {
                    size_t b0 = ((size_t)(t0 + xr0) * 4 + grp) * GRPBLK + (size_t)(bb & 31) * ROWB;
                    size_t b1 = ((size_t)(t0 + xr1) * 4 + grp) * GRPBLK + (size_t)(bb & 31) * ROWB;
                    sh0 = g_seqblk + b0; sl0 = sh0 + HLO;
                    sh1 = g_seqblk + b1; sl1 = sh1 + HLO;
                }
                // chunk offset within source row image
                #define XOFF(c) (xflat ? (size_t)(c) * 128 \
                                       : (size_t)((c) >> 1) * SLICE + (size_t)((c) & 1) * 128)

                float acc[4][4];
                #pragma unroll
                for (int f = 0; f < 4; ++f)
                    #pragma unroll
                    for (int q = 0; q < 4; ++q) acc[f][q] = 0.f;

                {
                    const unsigned d0 = sbase + PS + xr0 * 144 + xs0 * 16;
                    const unsigned d1 = sbase + PS + xr1 * 144 + xs1 * 16;
                    CP_ASYNC16(d0,          sh0 + xs0 * 16);
                    CP_ASYNC16(d0 + PLANE,  sl0 + xs0 * 16);
                    CP_ASYNC16(d1,          sh1 + xs1 * 16);
                    CP_ASYNC16(d1 + PLANE,  sl1 + xs1 * 16);
                    CP_COMMIT();
                }

                #pragma unroll 1
                for (int c = 0; c < 8; ++c) {
                    CP_WAIT0();
                    __syncthreads();
                    if (c < 7) {
                        const size_t off = XOFF(c + 1);
                        const unsigned bufd = sbase + PS + ((c + 1) & 1) * BUFSTRIDE;
                        const unsigned d0 = bufd + xr0 * 144 + xs0 * 16;
                        const unsigned d1 = bufd + xr1 * 144 + xs1 * 16;
                        CP_ASYNC16(d0,          sh0 + off + xs0 * 16);
                        CP_ASYNC16(d0 + PLANE,  sl0 + off + xs0 * 16);
                        CP_ASYNC16(d1,          sh1 + off + xs1 * 16);
                        CP_ASYNC16(d1 + PLANE,  sl1 + off + xs1 * 16);
                        CP_COMMIT();
                    }
                    const unsigned bufo = sbase + PS + (c & 1) * BUFSTRIDE;
                    #pragma unroll
                    for (int q = 0; q < 4; ++q) {
                        unsigned ah[4], al[4];
                        ldsm4(ah, wA + c * 128 + q * 32);
                        ldsm4(al, wAlo + c * 128 + q * 32);
                        #pragma unroll
                        for (int u = 0; u < 2; ++u) {
                            unsigned bh[4], bl[4];
                            unsigned ba = bufo + pBx_rel + u * 2304 + q * 32;
                            ldsm4(bh, ba);
                            ldsm4(bl, ba + PLANE);
                            mma16816(acc[2 * u],     ah, bh[0], bh[1]);
                            mma16816(acc[2 * u],     al, bh[0], bh[1]);
                            mma16816(acc[2 * u],     ah, bl[0], bl[1]);
                            mma16816(acc[2 * u + 1], ah, bh[2], bh[3]);
                            mma16816(acc[2 * u + 1], al, bh[2], bh[3]);
                            mma16816(acc[2 * u + 1], ah, bl[2], bl[3]);
                        }
                    }
                }
                #undef XOFF

                // store gx tile: layout [t][b][gate]
                const int gr0g = gt * 64 + wg * 16 + (lane >> 2);
                #pragma unroll
                for (int f = 0; f < 4; ++f) {
                    int u = f >> 1, v2 = f & 1;
                    int tt = wsub * 32 + u * 16 + v2 * 8 + (lane & 3) * 2;
                    size_t base = ((size_t)(t0 + tt) * 128 + bb) * (size_t)G + gr0g;
                    __stcg(g_gx + base,                        acc[f][0]);
                    __stcg(g_gx + base + (size_t)128 * G,      acc[f][1]);
                    __stcg(g_gx + base + 8,                    acc[f][2]);
                    __stcg(g_gx + base + (size_t)128 * G + 8,  acc[f][3]);
                }
                __syncthreads();
            }
        }
        gbar_grp(++ep, grp);

        // ================= recurrent phase =================
        // stage W_hh: local row r -> gate row (r>>4)*512 + gt*16 + (r&15)
        for (int it = tid; it < 64 * 128; it += NTHR) {
            int r = it >> 7, c4 = it & 127;
            int grow = (r >> 4) * 512 + gt * 16 + (r & 15);
            float4 v = __ldg((const float4*)(w_hh + ((size_t)l * G + grow) * 512) + c4);
            uint2 hi, lo;
            split4(v, hi, lo);
            *(uint2*)(sm + WS_HI + r * 1040 + c4 * 8) = hi;
            *(uint2*)(sm + WS_LO + r * 1040 + c4 * 8) = lo;
        }
        __syncthreads();

        // hoist this warp's W_hh fragments into registers (once per layer)
        unsigned ah[8][4], al[8][4];
        #pragma unroll
        for (int c = 0; c < 8; ++c) {
            ldsm4(ah[c], wAr + c * 32);
            ldsm4(al[c], wArlo + c * 32);
        }
        __syncthreads();   // W smem dead; stage region reused

        float bias[4];
        #pragma unroll
        for (int g = 0; g < 4; ++g)
            bias[g] = __ldg(b_ih + (size_t)l * G + g * 512 + egh)
                    + __ldg(b_hh + (size_t)l * G + g * 512 + egh);
        float creg = __ldg(c0 + (size_t)l * BH + (size_t)eb * 512 + egh);
        const float* gx_base = g_gx + (size_t)eb * G + egh;   // [t][b][gate]

        float* const gbuf = (float*)(sm + REC_STG) + rws * GBUF_STRIDE;
        const int gr = rwg * 16 + (lane >> 2);
        const int gc = (lane & 3) * 2;
        const int es = egh >> 7, ekl = egh & 127;   // EW h-write slice coords

        for (int t = 0; t < T; ++t) {
            // gx prefetch (independent of all waits)
            const float* gxt = gx_base + (size_t)t * (128 * G);
            float gx0 = __ldcg(gxt);
            float gx1 = __ldcg(gxt + 512);
            float gx2 = __ldcg(gxt + 1024);
            float gx3 = __ldcg(gxt + 1536);

            // slice issuer warp: poll 8 producers of slice rws, then fire its TMA
            if (rwg == rws) {
                if (t > 0) {
                    const unsigned long long tgt = ep + (unsigned long long)t;
                    bool done = (lane < 8)
                        ? (ldvol(&g_flags[grp * 32 + rws * 8 + lane]) >= tgt) : true;
                    while (!__all_sync(0xffffffffu, done)) {
                        done = (lane < 8)
                            ? (ldvol(&g_flags[grp * 32 + rws * 8 + lane]) >= tgt) : true;
                    }
                }
                if (lane == 0) {
                    const unsigned char* src = (t == 0)
                        ? g_h0blk + ((size_t)(l * 4 + grp)) * GRPBLK + (size_t)rws * SLICE
                        : g_seqblk + ((size_t)(t - 1) * 4 + grp) * GRPBLK + (size_t)rws * SLICE;
                    asm volatile("mbarrier.arrive.expect_tx.shared.b64 _, [%0], %1;"
                                 :: "r"(mbar_s), "r"((unsigned)SLICE) : "memory");
                    asm volatile(
                        "cp.async.bulk.shared::cluster.global.mbarrier::complete_tx::bytes "
                        "[%0], [%1], %2, [%3];"
                        :: "r"(sbase + REC_STG + rws * SLICE), "l"(src),
                           "r"((unsigned)SLICE), "r"(mbar_s)
                        : "memory");
                }
            }

            // consumers wait only on their slice's mbarrier, then mma immediately
            mbar_wait(mbar_s, mpar);

            float a0[4][4], a1[4][4];
            #pragma unroll
            for (int nt = 0; nt < 4; ++nt)
                #pragma unroll
                for (int q = 0; q < 4; ++q) { a0[nt][q] = 0.f; a1[nt][q] = 0.f; }

            #pragma unroll
            for (int nt = 0; nt < 4; ++nt) {
                const unsigned bbase = pBr + nt * (8 * ROWB);
                #pragma unroll
                for (int c2 = 0; c2 < 4; ++c2) {
                    unsigned bh[4], bl[4];
                    ldsm4(bh, bbase + c2 * 64);
                    ldsm4(bl, bbase + c2 * 64 + HLO);
                    mma16816(a0[nt], ah[2 * c2],     bh[0], bh[1]);
                    mma16816(a1[nt], al[2 * c2],     bh[0], bh[1]);
                    mma16816(a1[nt], ah[2 * c2],     bl[0], bl[1]);
                    mma16816(a0[nt], ah[2 * c2 + 1], bh[2], bh[3]);
                    mma16816(a1[nt], al[2 * c2 + 1], bh[2], bh[3]);
                    mma16816(a1[nt], ah[2 * c2 + 1], bl[2], bl[3]);
                }
            }
            __syncthreads();   // all mma done -> stage slices 0/1 reusable as gbuf

            #pragma unroll
            for (int nt = 0; nt < 4; ++nt) {
                *(float2*)&gbuf[gr * 34 + nt * 8 + gc] =
                    make_float2(a0[nt][0] + a1[nt][0], a0[nt][1] + a1[nt][1]);
                *(float2*)&gbuf[(gr + 8) * 34 + nt * 8 + gc] =
                    make_float2(a0[nt][2] + a1[nt][2], a0[nt][3] + a1[nt][3]);
            }
            __syncthreads();

            // elementwise: sum 4 K-split buffers + gx + bias
            {
                float v0 = bias[0] + gx0;
                float v1 = bias[1] + gx1;
                float v2 = bias[2] + gx2;
                float v3 = bias[3] + gx3;
                #pragma unroll
                for (int s = 0; s < 4; ++s) {
                    const float* gb = (const float*)(sm + REC_STG) + s * GBUF_STRIDE;
                    v0 += gb[(0 * 16 + lh) * 34 + lb];
                    v1 += gb[(1 * 16 + lh) * 34 + lb];
                    v2 += gb[(2 * 16 + lh) * 34 + lb];
                    v3 += gb[(3 * 16 + lh) * 34 + lb];
                }
                float ig = sigf(v0), fg = sigf(v1), gg = tanhg(v2), og = sigf(v3);
                creg = fmaf(fg, creg, ig * gg);
                float hv = og * tanhg(creg);
                size_t d = (((size_t)t * 4 + grp) * 4 + es) * SLICE
                         + (size_t)lb * ROWB + (size_t)ekl * 2;
                __nv_bfloat16 hb = __float2bfloat16(hv);
                __nv_bfloat16 hw = __float2bfloat16(hv - __bfloat162float(hb));
                *(__nv_bfloat16*)(g_seqblk + d) = hb;
                *(__nv_bfloat16*)(g_seqblk + d + HLO) = hw;
                if (t == T - 1)
                    out[(size_t)l * BH + (size_t)eb * 512 + egh] = creg;
            }

            // publish h(t)
            __threadfence();
            __syncthreads();
            if (tid == 0) atomicExch(&g_flags[bid], ep + (unsigned long long)(t + 1));
            mpar ^= 1;
        }

        // drain: all group peers finished t = T-1 before next layer reads seq
        if (tid < 32) {
            while (ldvol(&g_flags[grp * 32 + tid]) < ep + (unsigned long long)T) { }
        }
        __threadfence();
        __syncthreads();
        ep += T;
    }
}

extern "C" void kernel_launch(void* const* d_in, const int* in_sizes, int n_in,
                              void* d_out, int out_size) {
    const float* x    = (const float*)d_in[0];
    const float* h0   = (const float*)d_in[1];
    const float* c0   = (const float*)d_in[2];
    const float* w_ih = (const float*)d_in[3];
    const float* w_hh = (const float*)d_in[4];
    const float* b_ih = (const float*)d_in[5];
    const float* b_hh = (const float*)d_in[6];
    float* out = (float*)d_out;

    cudaFuncSetAttribute(lstm_kernel,
                         cudaFuncAttributeMaxDynamicSharedMemorySize, SMEM_BYTES);
    lstm_kernel<<<NBLK, NTHR, SMEM_BYTES>>>(x, h0, c0, w_ih, w_hh, b_ih, b_hh, out);
}

// round 15
// speedup vs baseline: 1.5065x; 1.0481x over previous
#include <cuda_runtime.h>
#include <cuda_bf16.h>

#define L 4
#define B 128
#define T 1024
#define NI 512
#define H 512
#define G 2048
#define BH (B*H)

#define NBLK 128
#define NTHR 512

// ---- smem layout (bytes) ----
// W: 64 rows x 512k hi/lo planes, row stride 1040B
#define WS_HI 0
#define WS_LO 66560
// x-phase stage: 2 buffers x (hi+lo planes), plane = 128 rows x 144B
#define PS 133120
#define PLANE 18432
#define BUFSTRIDE 36864
// recurrent stage: 4 K-slices, each 17408B {hi 32x272, lo @+8704}
#define REC_STG 133120
#define SLICE 17408
#define HLO 8704
#define ROWB 272
#define GRPBLK (4*SLICE)
// K-split gate buffers overlay the DEAD W region during t-loop (W is in registers)
#define GBUF_STRIDE (64 * 34)
// 4 mbarriers (8B each) in reserved region untouched by either phase
#define MBAR_OFF 214528
#define SMEM_BYTES 215296

// ---- device scratch ----
__device__ __nv_bfloat16 g_x_hi[(size_t)B * T * NI];                 // [b][t][k] flat
__device__ __nv_bfloat16 g_x_lo[(size_t)B * T * NI];
__device__ __align__(128) unsigned char g_seqblk[(size_t)T * 4 * GRPBLK];  // [t][grp][s] sliced
__device__ __align__(128) unsigned char g_h0blk[(size_t)L * 4 * GRPBLK];   // [l][grp][s]
__device__ float g_gx[(size_t)B * T * G];                            // [t][b][gate]
__device__ unsigned long long g_flags[NBLK];

#define CP_ASYNC16(dst, src) \
    asm volatile("cp.async.cg.shared.global [%0], [%1], 16;" :: "r"(dst), "l"(src))
#define CP_COMMIT() asm volatile("cp.async.commit_group;" ::: "memory")
#define CP_WAIT0()  asm volatile("cp.async.wait_group 0;" ::: "memory")

__device__ __forceinline__ unsigned long long ldvol(const unsigned long long* p) {
    unsigned long long v;
    asm volatile("ld.volatile.global.u64 %0, [%1];" : "=l"(v) : "l"(p));
    return v;
}
__device__ __forceinline__ unsigned long long ldacq(const unsigned long long* p) {
    unsigned long long v;
    asm volatile("ld.acquire.gpu.global.u64 %0, [%1];" : "=l"(v) : "l"(p) : "memory");
    return v;
}
__device__ __forceinline__ void strel(unsigned long long* p, unsigned long long v) {
    asm volatile("st.release.gpu.global.u64 [%0], %1;" :: "l"(p), "l"(v) : "memory");
}

__device__ __forceinline__ void gbar_all(unsigned long long ep) {
    __syncthreads();
    __threadfence();
    if (threadIdx.x == 0) atomicExch(&g_flags[blockIdx.x], ep);
    if (threadIdx.x < NBLK) {
        while (ldvol(&g_flags[threadIdx.x]) < ep) { }
    }
    __threadfence();
    __syncthreads();
}

__device__ __forceinline__ void gbar_grp(unsigned long long ep, int grp) {
    __syncthreads();
    __threadfence();
    if (threadIdx.x == 0) atomicExch(&g_flags[blockIdx.x], ep);
    if (threadIdx.x < 32) {
        while (ldvol(&g_flags[grp * 32 + threadIdx.x]) < ep) { }
    }
    __threadfence();
    __syncthreads();
}

__device__ __forceinline__ void mbar_wait(unsigned mbar, unsigned phase) {
    asm volatile(
        "{\n\t"
        ".reg .pred P;\n\t"
        "WL_%=:\n\t"
        "mbarrier.try_wait.parity.acquire.cta.shared::cta.b64 P, [%0], %1;\n\t"
        "@!P bra WL_%=;\n\t"
        "}"
        :: "r"(mbar), "r"(phase) : "memory");
}

__device__ __forceinline__ void split4(float4 v, uint2& hi, uint2& lo) {
    __nv_bfloat16 h0 = __float2bfloat16(v.x), h1 = __float2bfloat16(v.y);
    __nv_bfloat16 h2 = __float2bfloat16(v.z), h3 = __float2bfloat16(v.w);
    __nv_bfloat16 l0 = __float2bfloat16(v.x - __bfloat162float(h0));
    __nv_bfloat16 l1 = __float2bfloat16(v.y - __bfloat162float(h1));
    __nv_bfloat16 l2 = __float2bfloat16(v.z - __bfloat162float(h2));
    __nv_bfloat16 l3 = __float2bfloat16(v.w - __bfloat162float(h3));
    hi.x = (unsigned)*(unsigned short*)&h0 | ((unsigned)*(unsigned short*)&h1 << 16);
    hi.y = (unsigned)*(unsigned short*)&h2 | ((unsigned)*(unsigned short*)&h3 << 16);
    lo.x = (unsigned)*(unsigned short*)&l0 | ((unsigned)*(unsigned short*)&l1 << 16);
    lo.y = (unsigned)*(unsigned short*)&l2 | ((unsigned)*(unsigned short*)&l3 << 16);
}

__device__ __forceinline__ void ldsm4(unsigned r[4], unsigned addr) {
    asm volatile("ldmatrix.sync.aligned.m8n8.x4.shared.b16 {%0,%1,%2,%3}, [%4];"
                 : "=r"(r[0]), "=r"(r[1]), "=r"(r[2]), "=r"(r[3]) : "r"(addr));
}

__device__ __forceinline__ void mma16816(float c[4], const unsigned a[4],
                                         unsigned b0, unsigned b1) {
    asm volatile(
        "mma.sync.aligned.m16n8k16.row.col.f32.bf16.bf16.f32 "
        "{%0,%1,%2,%3}, {%4,%5,%6,%7}, {%8,%9}, {%0,%1,%2,%3};"
        : "+f"(c[0]), "+f"(c[1]), "+f"(c[2]), "+f"(c[3])
        : "r"(a[0]), "r"(a[1]), "r"(a[2]), "r"(a[3]), "r"(b0), "r"(b1));
}

__device__ __forceinline__ float sigf(float x) { return 1.0f / (1.0f + __expf(-x)); }
__device__ __forceinline__ float tanhg(float x) { return 2.0f / (1.0f + __expf(-2.0f * x)) - 1.0f; }

__global__ void __launch_bounds__(NTHR, 1)
lstm_kernel(const float* __restrict__ x,
            const float* __restrict__ h0,
            const float* __restrict__ c0,
            const float* __restrict__ w_ih,
            const float* __restrict__ w_hh,
            const float* __restrict__ b_ih,
            const float* __restrict__ b_hh,
            float* __restrict__ out) {
    extern __shared__ char sm[];
    const unsigned sbase = (unsigned)__cvta_generic_to_shared(sm);

    const int tid = threadIdx.x, bid = blockIdx.x;
    const int lane = tid & 31, warp = tid >> 5;

    unsigned long long ep = ldvol(&g_flags[bid]);
    unsigned mpar = 0;   // mbarrier parity, flips once per recurrent step

    if (tid < 4)
        asm volatile("mbarrier.init.shared.b64 [%0], %1;"
                     :: "r"(sbase + MBAR_OFF + tid * 8), "r"(1u));

    // ---------------- prologue: split x (flat), h0 (sliced block format) ----------------
    {
        const size_t gt0 = (size_t)bid * NTHR + tid, gs = (size_t)NBLK * NTHR;
        const float4* xs = (const float4*)x;
        const size_t nx = (size_t)B * T * NI / 4;
        for (size_t i = gt0; i < nx; i += gs) {
            uint2 hi, lo;
            split4(__ldg(xs + i), hi, lo);
            ((uint2*)g_x_hi)[i] = hi;
            ((uint2*)g_x_lo)[i] = lo;
        }
        const float4* hs = (const float4*)h0;
        const size_t nh = (size_t)L * BH / 4;
        for (size_t i = gt0; i < nh; i += gs) {
            uint2 hi, lo;
            split4(__ldg(hs + i), hi, lo);
            size_t e = i * 4;
            int l_ = (int)(e >> 16);
            int b_ = (int)((e >> 9) & 127);
            int k_ = (int)(e & 511);
            int s_ = k_ >> 7, kl = k_ & 127;
            size_t d = ((size_t)(l_ * 4 + (b_ >> 5)) * 4 + s_) * SLICE
                     + (size_t)(b_ & 31) * ROWB + (size_t)kl * 2;
            *(uint2*)(g_h0blk + d) = hi;
            *(uint2*)(g_h0blk + d + HLO) = lo;
        }
    }
    gbar_all(++ep);

    const int gt = bid & 31;    // gate/h tile
    const int grp = bid >> 5;   // batch group (32 batches)

    // x-phase warp roles
    const int wg = warp >> 2, wsub = warp & 3;
    const unsigned wA = sbase + WS_HI + (unsigned)((wg * 16 + (lane & 15)) * 1040 + (lane >> 4) * 16);
    const unsigned wAlo = wA + (WS_LO - WS_HI);
    const unsigned pBx_rel = (unsigned)((wsub * 32 + (lane & 7) + ((lane >> 4) << 3)) * 144
                                        + ((lane >> 3) & 1) * 16);
    const int xr0 = tid >> 3, xs0 = tid & 7;
    const int xr1 = (tid + 512) >> 3, xs1 = tid & 7;

    // recurrent warp roles: rwg = m-stripe, rws = K-slice; slice warps span 4 SMSPs
    const int rwg = warp & 3, rws = warp >> 2;
    const unsigned wAr = sbase + WS_HI + (unsigned)((rwg * 16 + (lane & 15)) * 1040
                                                    + (lane >> 4) * 16 + rws * 256);
    const unsigned wArlo = wAr + (WS_LO - WS_HI);
    const unsigned pBr = sbase + REC_STG + (unsigned)(rws * SLICE
                       + (lane & 7) * ROWB + (lane >> 3) * 16);
    const unsigned mbar_s = sbase + MBAR_OFF + rws * 8;

    const int lh = tid & 15, lb = tid >> 4;
    const int eb = grp * 32 + lb;
    const int egh = gt * 16 + lh;

    for (int l = 0; l < L; ++l) {
        const bool xflat = (l == 0);
        // ================= x-phase: gx = W_ih * input_seq =================
        for (int it = tid; it < 64 * 128; it += NTHR) {
            int r = it >> 7, c4 = it & 127;
            float4 v = __ldg((const float4*)(w_ih + ((size_t)l * G + gt * 64 + r) * 512) + c4);
            uint2 hi, lo;
            split4(v, hi, lo);
            *(uint2*)(sm + WS_HI + r * 1040 + c4 * 8) = hi;
            *(uint2*)(sm + WS_LO + r * 1040 + c4 * 8) = lo;
        }
        __syncthreads();

        {
            for (int m = 0; m < 256; ++m) {
                const int bb = grp * 32 + (m >> 3);
                const int t0 = (m & 7) * 128;

                const unsigned char *sh0, *sl0, *sh1, *sl1;
                if (xflat) {
                    size_t rb0 = (((size_t)bb << 10) + (size_t)(t0 + xr0)) * 512;
                    size_t rb1 = (((size_t)bb << 10) + (size_t)(t0 + xr1)) * 512;
                    sh0 = (const unsigned char*)(g_x_hi + rb0);
                    sl0 = (const unsigned char*)(g_x_lo + rb0);
                    sh1 = (const unsigned char*)(g_x_hi + rb1);
                    sl1 = (const unsigned char*)(g_x_lo + rb1);
                } else {
                    size_t b0 = ((size_t)(t0 + xr0) * 4 + grp) * GRPBLK + (size_t)(bb & 31) * ROWB;
                    size_t b1 = ((size_t)(t0 + xr1) * 4 + grp) * GRPBLK + (size_t)(bb & 31) * ROWB;
                    sh0 = g_seqblk + b0; sl0 = sh0 + HLO;
                    sh1 = g_seqblk + b1; sl1 = sh1 + HLO;
                }
                #define XOFF(c) (xflat ? (size_t)(c) * 128 \
                                       : (size_t)((c) >> 1) * SLICE + (size_t)((c) & 1) * 128)

                float acc[4][4];
                #pragma unroll
                for (int f = 0; f < 4; ++f)
                    #pragma unroll
                    for (int q = 0; q < 4; ++q) acc[f][q] = 0.f;

                {
                    const unsigned d0 = sbase + PS + xr0 * 144 + xs0 * 16;
                    const unsigned d1 = sbase + PS + xr1 * 144 + xs1 * 16;
                    CP_ASYNC16(d0,          sh0 + xs0 * 16);
                    CP_ASYNC16(d0 + PLANE,  sl0 + xs0 * 16);
                    CP_ASYNC16(d1,          sh1 + xs1 * 16);
                    CP_ASYNC16(d1 + PLANE,  sl1 + xs1 * 16);
                    CP_COMMIT();
                }

                #pragma unroll 1
                for (int c = 0; c < 8; ++c) {
                    CP_WAIT0();
                    __syncthreads();
                    if (c < 7) {
                        const size_t off = XOFF(c + 1);
                        const unsigned bufd = sbase + PS + ((c + 1) & 1) * BUFSTRIDE;
                        const unsigned d0 = bufd + xr0 * 144 + xs0 * 16;
                        const unsigned d1 = bufd + xr1 * 144 + xs1 * 16;
                        CP_ASYNC16(d0,          sh0 + off + xs0 * 16);
                        CP_ASYNC16(d0 + PLANE,  sl0 + off + xs0 * 16);
                        CP_ASYNC16(d1,          sh1 + off + xs1 * 16);
                        CP_ASYNC16(d1 + PLANE,  sl1 + off + xs1 * 16);
                        CP_COMMIT();
                    }
                    const unsigned bufo = sbase + PS + (c & 1) * BUFSTRIDE;
                    #pragma unroll
                    for (int q = 0; q < 4; ++q) {
                        unsigned ah[4], al[4];
                        ldsm4(ah, wA + c * 128 + q * 32);
                        ldsm4(al, wAlo + c * 128 + q * 32);
                        #pragma unroll
                        for (int u = 0; u < 2; ++u) {
                            unsigned bh[4], bl[4];
                            unsigned ba = bufo + pBx_rel + u * 2304 + q * 32;
                            ldsm4(bh, ba);
                            ldsm4(bl, ba + PLANE);
                            mma16816(acc[2 * u],     ah, bh[0], bh[1]);
                            mma16816(acc[2 * u],     al, bh[0], bh[1]);
                            mma16816(acc[2 * u],     ah, bl[0], bl[1]);
                            mma16816(acc[2 * u + 1], ah, bh[2], bh[3]);
                            mma16816(acc[2 * u + 1], al, bh[2], bh[3]);
                            mma16816(acc[2 * u + 1], ah, bl[2], bl[3]);
                        }
                    }
                }
                #undef XOFF

                // store gx tile: layout [t][b][gate]
                const int gr0g = gt * 64 + wg * 16 + (lane >> 2);
                #pragma unroll
                for (int f = 0; f < 4; ++f) {
                    int u = f >> 1, v2 = f & 1;
                    int tt = wsub * 32 + u * 16 + v2 * 8 + (lane & 3) * 2;
                    size_t base = ((size_t)(t0 + tt) * 128 + bb) * (size_t)G + gr0g;
                    __stcg(g_gx + base,                        acc[f][0]);
                    __stcg(g_gx + base + (size_t)128 * G,      acc[f][1]);
                    __stcg(g_gx + base + 8,                    acc[f][2]);
                    __stcg(g_gx + base + (size_t)128 * G + 8,  acc[f][3]);
                }
                __syncthreads();
            }
        }
        gbar_grp(++ep, grp);

        // ================= recurrent phase =================
        // stage W_hh: local row r -> gate row (r>>4)*512 + gt*16 + (r&15)
        for (int it = tid; it < 64 * 128; it += NTHR) {
            int r = it >> 7, c4 = it & 127;
            int grow = (r >> 4) * 512 + gt * 16 + (r & 15);
            float4 v = __ldg((const float4*)(w_hh + ((size_t)l * G + grow) * 512) + c4);
            uint2 hi, lo;
            split4(v, hi, lo);
            *(uint2*)(sm + WS_HI + r * 1040 + c4 * 8) = hi;
            *(uint2*)(sm + WS_LO + r * 1040 + c4 * 8) = lo;
        }
        __syncthreads();

        // hoist this warp's W_hh fragments into registers (once per layer)
        unsigned ah[8][4], al[8][4];
        #pragma unroll
        for (int c = 0; c < 8; ++c) {
            ldsm4(ah[c], wAr + c * 32);
            ldsm4(al[c], wArlo + c * 32);
        }
        __syncthreads();   // W smem dead during t-loop -> gbufs overlay it

        float bias[4];
        #pragma unroll
        for (int g = 0; g < 4; ++g)
            bias[g] = __ldg(b_ih + (size_t)l * G + g * 512 + egh)
                    + __ldg(b_hh + (size_t)l * G + g * 512 + egh);
        float creg = __ldg(c0 + (size_t)l * BH + (size_t)eb * 512 + egh);
        const float* gx_base = g_gx + (size_t)eb * G + egh;   // [t][b][gate]

        // gbuf now overlays the dead W region (no conflict with stage slices)
        float* const gbuf = (float*)sm + rws * GBUF_STRIDE;
        const int gr = rwg * 16 + (lane >> 2);
        const int gc = (lane & 3) * 2;
        const int es = egh >> 7, ekl = egh & 127;   // EW h-write slice coords

        for (int t = 0; t < T; ++t) {
            // gx prefetch (independent of all waits)
            const float* gxt = gx_base + (size_t)t * (128 * G);
            float gx0 = __ldcg(gxt);
            float gx1 = __ldcg(gxt + 512);
            float gx2 = __ldcg(gxt + 1024);
            float gx3 = __ldcg(gxt + 1536);

            // slice issuer warp: poll 8 producers of slice rws (acquire), fire TMA
            if (rwg == rws) {
                if (t > 0) {
                    const unsigned long long tgt = ep + (unsigned long long)t;
                    bool done = (lane < 8)
                        ? (ldacq(&g_flags[grp * 32 + rws * 8 + lane]) >= tgt) : true;
                    while (!__all_sync(0xffffffffu, done)) {
                        done = (lane < 8)
                            ? (ldacq(&g_flags[grp * 32 + rws * 8 + lane]) >= tgt) : true;
                    }
                }
                if (lane == 0) {
                    const unsigned char* src = (t == 0)
                        ? g_h0blk + ((size_t)(l * 4 + grp)) * GRPBLK + (size_t)rws * SLICE
                        : g_seqblk + ((size_t)(t - 1) * 4 + grp) * GRPBLK + (size_t)rws * SLICE;
                    asm volatile("mbarrier.arrive.expect_tx.shared.b64 _, [%0], %1;"
                                 :: "r"(mbar_s), "r"((unsigned)SLICE) : "memory");
                    asm volatile(
                        "cp.async.bulk.shared::cluster.global.mbarrier::complete_tx::bytes "
                        "[%0], [%1], %2, [%3];"
                        :: "r"(sbase + REC_STG + rws * SLICE), "l"(src),
                           "r"((unsigned)SLICE), "r"(mbar_s)
                        : "memory");
                }
            }

            // consumers wait only on their slice's mbarrier, then mma immediately
            mbar_wait(mbar_s, mpar);

            float a0[4][4], a1[4][4];
            #pragma unroll
            for (int nt = 0; nt < 4; ++nt)
                #pragma unroll
                for (int q = 0; q < 4; ++q) { a0[nt][q] = 0.f; a1[nt][q] = 0.f; }

            #pragma unroll
            for (int nt = 0; nt < 4; ++nt) {
                const unsigned bbase = pBr + nt * (8 * ROWB);
                #pragma unroll
                for (int c2 = 0; c2 < 4; ++c2) {
                    unsigned bh[4], bl[4];
                    ldsm4(bh, bbase + c2 * 64);
                    ldsm4(bl, bbase + c2 * 64 + HLO);
                    mma16816(a0[nt], ah[2 * c2],     bh[0], bh[1]);
                    mma16816(a1[nt], al[2 * c2],     bh[0], bh[1]);
                    mma16816(a1[nt], ah[2 * c2],     bl[0], bl[1]);
                    mma16816(a0[nt], ah[2 * c2 + 1], bh[2], bh[3]);
                    mma16816(a1[nt], al[2 * c2 + 1], bh[2], bh[3]);
                    mma16816(a1[nt], ah[2 * c2 + 1], bl[2], bl[3]);
                }
            }

            // gbuf write immediately after own mma (no block-wide join here;
            // gbuf lives in the dead W region, not the stage slices)
            #pragma unroll
            for (int nt = 0; nt < 4; ++nt) {
                *(float2*)&gbuf[gr * 34 + nt * 8 + gc] =
                    make_float2(a0[nt][0] + a1[nt][0], a0[nt][1] + a1[nt][1]);
                *(float2*)&gbuf[(gr + 8) * 34 + nt * 8 + gc] =
                    make_float2(a0[nt][2] + a1[nt][2], a0[nt][3] + a1[nt][3]);
            }
            __syncthreads();   // single join: all gbufs ready for EW

            // elementwise: sum 4 K-split buffers + gx + bias
            {
                float v0 = bias[0] + gx0;
                float v1 = bias[1] + gx1;
                float v2 = bias[2] + gx2;
                float v3 = bias[3] + gx3;
                #pragma unroll
                for (int s = 0; s < 4; ++s) {
                    const float* gb = (const float*)sm + s * GBUF_STRIDE;
                    v0 += gb[(0 * 16 + lh) * 34 + lb];
                    v1 += gb[(1 * 16 + lh) * 34 + lb];
                    v2 += gb[(2 * 16 + lh) * 34 + lb];
                    v3 += gb[(3 * 16 + lh) * 34 + lb];
                }
                float ig = sigf(v0), fg = sigf(v1), gg = tanhg(v2), og = sigf(v3);
                creg = fmaf(fg, creg, ig * gg);
                float hv = og * tanhg(creg);
                size_t d = (((size_t)t * 4 + grp) * 4 + es) * SLICE
                         + (size_t)lb * ROWB + (size_t)ekl * 2;
                __nv_bfloat16 hb = __float2bfloat16(hv);
                __nv_bfloat16 hw = __float2bfloat16(hv - __bfloat162float(hb));
                *(__nv_bfloat16*)(g_seqblk + d) = hb;
                *(__nv_bfloat16*)(g_seqblk + d + HLO) = hw;
                if (t == T - 1)
                    out[(size_t)l * BH + (size_t)eb * 512 + egh] = creg;
            }

            // publish h(t): bar.sync + tid0 release store (no membar.gl)
            __syncthreads();
            if (tid == 0) strel(&g_flags[bid], ep + (unsigned long long)(t + 1));
            mpar ^= 1;
        }

        // drain: all group peers finished t = T-1 before next layer reads seq
        if (tid < 32) {
            while (ldacq(&g_flags[grp * 32 + tid]) < ep + (unsigned long long)T) { }
        }
        __syncthreads();
        ep += T;
    }
}

extern "C" void kernel_launch(void* const* d_in, const int* in_sizes, int n_in,
                              void* d_out, int out_size) {
    const float* x    = (const float*)d_in[0];
    const float* h0   = (const float*)d_in[1];
    const float* c0   = (const float*)d_in[2];
    const float* w_ih = (const float*)d_in[3];
    const float* w_hh = (const float*)d_in[4];
    const float* b_ih = (const float*)d_in[5];
    const float* b_hh = (const float*)d_in[6];
    float* out = (float*)d_out;

    cudaFuncSetAttribute(lstm_kernel,
                         cudaFuncAttributeMaxDynamicSharedMemorySize, SMEM_BYTES);
    lstm_kernel<<<NBLK, NTHR, SMEM_BYTES>>>(x, h0, c0, w_ih, w_hh, b_ih, b_hh, out);
}